// round 2
// baseline (speedup 1.0000x reference)
#include <cuda_runtime.h>
#include <cstdint>

// Problem dims
#define NB 8192   // tokens
#define NF 2048   // features (= K of every GEMM here)
#define NE 16     // experts
#define NU 2048   // expert hidden / d_model
#define NDM 2048
#define NH 16
#define NDEPTH 128

// ---------------- device scratch (no allocations allowed) ----------------
__device__ float g_moe[(size_t)NB * NU];
__device__ float g_q [(size_t)NB * NDM];
__device__ float g_k [(size_t)NB * NDM];
__device__ float g_v [(size_t)NB * NDM];
__device__ float g_att[(size_t)NB * NDM];
__device__ int   g_counts[NE];
__device__ int   g_rows [NE * NB];
__device__ float g_gates[NE * NB];

// ---------------- small helpers ----------------
__device__ __forceinline__ uint32_t f2tf(float x) {
    uint32_t r;
    asm("cvt.rna.tf32.f32 %0, %1;" : "=r"(r) : "f"(x));
    return r;
}

__device__ __forceinline__ void mma8(float* c, const uint32_t* a, const uint32_t* b) {
    asm volatile(
        "mma.sync.aligned.m16n8k8.row.col.f32.tf32.tf32.f32 "
        "{%0,%1,%2,%3},{%4,%5,%6,%7},{%8,%9},{%0,%1,%2,%3};"
        : "+f"(c[0]), "+f"(c[1]), "+f"(c[2]), "+f"(c[3])
        : "r"(a[0]), "r"(a[1]), "r"(a[2]), "r"(a[3]), "r"(b[0]), "r"(b[1]));
}

__device__ __forceinline__ uint32_t smem_u32(const void* p) {
    return (uint32_t)__cvta_generic_to_shared(p);
}

#define CPA16(dst, src) \
    asm volatile("cp.async.cg.shared.global [%0], [%1], 16;" :: "r"(dst), "l"(src))

// ---------------- zero scratch + counts ----------------
__global__ void zero_kernel() {
    size_t n = (size_t)NB * NU / 4;
    float4* p = (float4*)g_moe;
    float4 z = make_float4(0.f, 0.f, 0.f, 0.f);
    for (size_t i = (size_t)blockIdx.x * blockDim.x + threadIdx.x; i < n;
         i += (size_t)gridDim.x * blockDim.x)
        p[i] = z;
    if (blockIdx.x == 0 && threadIdx.x < NE) g_counts[threadIdx.x] = 0;
}

// ---------------- router: fp32 logits, softmax, top-2, token lists ----------------
__global__ void router_kernel(const float* __restrict__ x,
                              const float* __restrict__ rw,
                              const float* __restrict__ rb) {
    const int b = blockIdx.x;
    const int tid = threadIdx.x;  // 128 threads
    float part[NE];
#pragma unroll
    for (int e = 0; e < NE; e++) part[e] = 0.f;

    const float* xr = x + (size_t)b * NF;
    for (int f = tid; f < NF; f += 128) {
        float xv = xr[f];
        const float4* w4 = (const float4*)(rw + (size_t)f * NE);
#pragma unroll
        for (int e4 = 0; e4 < 4; e4++) {
            float4 w = w4[e4];
            part[e4 * 4 + 0] += xv * w.x;
            part[e4 * 4 + 1] += xv * w.y;
            part[e4 * 4 + 2] += xv * w.z;
            part[e4 * 4 + 3] += xv * w.w;
        }
    }

    __shared__ float red[NE][128];
#pragma unroll
    for (int e = 0; e < NE; e++) red[e][tid] = part[e];
    __syncthreads();

    __shared__ float lg[NE];
    if (tid < NE) {
        float s = 0.f;
        for (int j = 0; j < 128; j++) s += red[tid][j];
        lg[tid] = s + rb[tid];
    }
    __syncthreads();

    if (tid == 0) {
        float mx = lg[0];
#pragma unroll
        for (int e = 1; e < NE; e++) mx = fmaxf(mx, lg[e]);
        float p[NE];
        float s = 0.f;
#pragma unroll
        for (int e = 0; e < NE; e++) { p[e] = expf(lg[e] - mx); s += p[e]; }
        // top-1: strict > keeps first index on ties (matches jax top_k)
        int e0 = 0; float b0 = p[0];
#pragma unroll
        for (int e = 1; e < NE; e++) if (p[e] > b0) { b0 = p[e]; e0 = e; }
        int e1 = -1; float b1 = -1.f;
#pragma unroll
        for (int e = 0; e < NE; e++)
            if (e != e0 && p[e] > b1) { b1 = p[e]; e1 = e; }
        float inv = 1.f / s;
        int pos = atomicAdd(&g_counts[e0], 1);
        g_rows [e0 * NB + pos] = b;
        g_gates[e0 * NB + pos] = b0 * inv;
        pos = atomicAdd(&g_counts[e1], 1);
        g_rows [e1 * NB + pos] = b;
        g_gates[e1 * NB + pos] = b1 * inv;
    }
}

// ---------------- tf32 GEMM: 128x128x16 tiles, cp.async double buffer ----------------
#define BM 128
#define BN 128
#define BK 16
#define LDA (BK + 4)   // 20 floats -> 80B rows (16B aligned, LDS conflict-free)
#define LDB (BN + 8)   // 136 floats -> 544B rows (16B aligned, conflict-free)
#define NTHREADS 256
#define NKITER (NF / BK)  // 128

// MOE=true : A rows gathered via g_rows, epilogue gate*relu(acc+bias) atomicAdd-scattered
// MOE=false: plain C = A@W + bias
template <bool MOE>
__global__ __launch_bounds__(NTHREADS) void gemm_kernel(
    const float* __restrict__ A, const float* __restrict__ W,
    const float* __restrict__ bias, float* __restrict__ C) {
    __shared__ float As[2][BM][LDA];
    __shared__ float Bs[2][BK][LDB];
    __shared__ int rows_s[BM];
    __shared__ float gate_s[BM];

    const int tid = threadIdx.x;
    const int n0blk = blockIdx.x * BN;
    const int m0blk = blockIdx.y * BM;

    int cnt = BM;
    const float* Wp = W;
    const float* biasp = bias;
    if (MOE) {
        const int e = blockIdx.z;
        const int ce = g_counts[e];
        cnt = ce - m0blk;
        if (cnt <= 0) return;
        Wp = W + (size_t)e * NF * NU;
        biasp = bias + e * NU;
        if (tid < BM) {
            bool v = tid < cnt;
            rows_s[tid] = v ? g_rows [e * NB + m0blk + tid] : 0;
            gate_s[tid] = v ? g_gates[e * NB + m0blk + tid] : 0.f;
        }
        __syncthreads();
    }

    const int lane = tid & 31, warp = tid >> 5;
    const int wm = (warp >> 2) * 64;
    const int wn = (warp & 3) * 32;
    const int g = lane >> 2, tig = lane & 3;

    float acc[4][4][4];
#pragma unroll
    for (int mt = 0; mt < 4; mt++)
#pragma unroll
        for (int nt = 0; nt < 4; nt++)
#pragma unroll
            for (int i = 0; i < 4; i++) acc[mt][nt][i] = 0.f;

    auto loadA = [&](int buf, int k0) {
#pragma unroll
        for (int i = 0; i < 2; i++) {
            int c = tid + i * NTHREADS;      // 0..511
            int m = c >> 2, kc = (c & 3) * 4;
            const float* src;
            if (MOE) src = A + (size_t)rows_s[m] * NF + k0 + kc;
            else     src = A + (size_t)(m0blk + m) * NF + k0 + kc;
            CPA16(smem_u32(&As[buf][m][kc]), src);
        }
    };
    auto loadB = [&](int buf, int k0) {
#pragma unroll
        for (int i = 0; i < 2; i++) {
            int c = tid + i * NTHREADS;      // 0..511
            int kr = c >> 5, nc = (c & 31) * 4;
            const float* src = Wp + (size_t)(k0 + kr) * NU + n0blk + nc;
            CPA16(smem_u32(&Bs[buf][kr][nc]), src);
        }
    };

    loadA(0, 0);
    loadB(0, 0);
    asm volatile("cp.async.commit_group;");

    for (int kt = 0; kt < NKITER; kt++) {
        const int cb = kt & 1, nb = (kt + 1) & 1;
        if (kt + 1 < NKITER) { loadA(nb, (kt + 1) * BK); loadB(nb, (kt + 1) * BK); }
        asm volatile("cp.async.commit_group;");
        asm volatile("cp.async.wait_group 1;");
        __syncthreads();

#pragma unroll
        for (int ks = 0; ks < 2; ks++) {
            const int k8 = ks * 8;
            uint32_t a[4][4], b[4][2];
#pragma unroll
            for (int mt = 0; mt < 4; mt++) {
                int mr = wm + mt * 16 + g;
                a[mt][0] = f2tf(As[cb][mr    ][k8 + tig]);
                a[mt][1] = f2tf(As[cb][mr + 8][k8 + tig]);
                a[mt][2] = f2tf(As[cb][mr    ][k8 + tig + 4]);
                a[mt][3] = f2tf(As[cb][mr + 8][k8 + tig + 4]);
            }
#pragma unroll
            for (int nt = 0; nt < 4; nt++) {
                int nc = wn + nt * 8 + g;
                b[nt][0] = f2tf(Bs[cb][k8 + tig    ][nc]);
                b[nt][1] = f2tf(Bs[cb][k8 + tig + 4][nc]);
            }
#pragma unroll
            for (int mt = 0; mt < 4; mt++)
#pragma unroll
                for (int nt = 0; nt < 4; nt++) mma8(acc[mt][nt], a[mt], b[nt]);
        }
        __syncthreads();
    }

    const int cntc = MOE ? (cnt < BM ? cnt : BM) : BM;
#pragma unroll
    for (int mt = 0; mt < 4; mt++) {
#pragma unroll
        for (int nt = 0; nt < 4; nt++) {
            int r0 = wm + mt * 16 + g;
            int r1 = r0 + 8;
            int cg0 = n0blk + wn + nt * 8 + 2 * tig;
            int cg1 = cg0 + 1;
            float bz0 = biasp[cg0], bz1 = biasp[cg1];
            if (MOE) {
                if (r0 < cntc) {
                    int tok = rows_s[r0]; float gt = gate_s[r0];
                    atomicAdd(&C[(size_t)tok * NU + cg0], gt * fmaxf(acc[mt][nt][0] + bz0, 0.f));
                    atomicAdd(&C[(size_t)tok * NU + cg1], gt * fmaxf(acc[mt][nt][1] + bz1, 0.f));
                }
                if (r1 < cntc) {
                    int tok = rows_s[r1]; float gt = gate_s[r1];
                    atomicAdd(&C[(size_t)tok * NU + cg0], gt * fmaxf(acc[mt][nt][2] + bz0, 0.f));
                    atomicAdd(&C[(size_t)tok * NU + cg1], gt * fmaxf(acc[mt][nt][3] + bz1, 0.f));
                }
            } else {
                size_t ro0 = (size_t)(m0blk + r0) * NU;
                size_t ro1 = (size_t)(m0blk + r1) * NU;
                C[ro0 + cg0] = acc[mt][nt][0] + bz0;
                C[ro0 + cg1] = acc[mt][nt][1] + bz1;
                C[ro1 + cg0] = acc[mt][nt][2] + bz0;
                C[ro1 + cg1] = acc[mt][nt][3] + bz1;
            }
        }
    }
}

// ---------------- per-token single-latent attention ----------------
__global__ void attn_kernel() {
    const int b = blockIdx.x;
    const int tid = threadIdx.x;  // 256
    const int warp = tid >> 5, lane = tid & 31;

    __shared__ float sc[NH];
    const float4* q4 = (const float4*)(g_q + (size_t)b * NDM);
    const float4* k4 = (const float4*)(g_k + (size_t)b * NDM);
    const float4* v4 = (const float4*)(g_v + (size_t)b * NDM);
    float4* o4 = (float4*)(g_att + (size_t)b * NDM);

#pragma unroll
    for (int i = 0; i < 2; i++) {
        int h = warp * 2 + i;
        float4 qv = q4[h * 32 + lane];
        float4 kv = k4[h * 32 + lane];
        float s = qv.x * kv.x + qv.y * kv.y + qv.z * kv.z + qv.w * kv.w;
#pragma unroll
        for (int o = 16; o; o >>= 1) s += __shfl_xor_sync(0xffffffffu, s, o);
        if (lane == 0) sc[h] = s * 0.08838834764831845f;  // 1/sqrt(128)
    }
    __syncthreads();

    float mx = sc[0];
#pragma unroll
    for (int h = 1; h < NH; h++) mx = fmaxf(mx, sc[h]);
    float ssum = 0.f;
#pragma unroll
    for (int h = 0; h < NH; h++) ssum += expf(sc[h] - mx);
    float inv = 1.f / ssum;
    // this thread only touches heads (warp) and (warp+8)
    float a0 = expf(sc[warp] - mx) * inv;
    float a1 = expf(sc[warp + 8] - mx) * inv;

    {
        float4 vv = v4[tid];            // head = tid>>5 = warp
        o4[tid] = make_float4(a0 * vv.x, a0 * vv.y, a0 * vv.z, a0 * vv.w);
    }
    {
        float4 vv = v4[tid + 256];      // head = warp + 8
        o4[tid + 256] = make_float4(a1 * vv.x, a1 * vv.y, a1 * vv.z, a1 * vv.w);
    }
}

// ---------------- launcher ----------------
extern "C" void kernel_launch(void* const* d_in, const int* in_sizes, int n_in,
                              void* d_out, int out_size) {
    const float* x  = (const float*)d_in[0];
    const float* rw = (const float*)d_in[1];
    const float* rb = (const float*)d_in[2];
    const float* ew = (const float*)d_in[3];
    const float* eb = (const float*)d_in[4];
    const float* wq = (const float*)d_in[5];
    const float* bq = (const float*)d_in[6];
    const float* wk = (const float*)d_in[7];
    const float* bk = (const float*)d_in[8];
    const float* wv = (const float*)d_in[9];
    const float* bv = (const float*)d_in[10];
    const float* wo = (const float*)d_in[11];
    const float* bo = (const float*)d_in[12];
    float* out = (float*)d_out;

    float *p_moe, *p_q, *p_k, *p_v, *p_att;
    cudaGetSymbolAddress((void**)&p_moe, g_moe);
    cudaGetSymbolAddress((void**)&p_q,   g_q);
    cudaGetSymbolAddress((void**)&p_k,   g_k);
    cudaGetSymbolAddress((void**)&p_v,   g_v);
    cudaGetSymbolAddress((void**)&p_att, g_att);

    zero_kernel<<<2048, 256>>>();
    router_kernel<<<NB, 128>>>(x, rw, rb);

    // sparse MoE: grid z = expert, y = token-tile (overprovisioned, early exit)
    gemm_kernel<true><<<dim3(NU / BN, NB / BM, NE), NTHREADS>>>(x, ew, eb, p_moe);

    gemm_kernel<false><<<dim3(NDM / BN, NB / BM), NTHREADS>>>(p_moe, wq, bq, p_q);
    gemm_kernel<false><<<dim3(NDM / BN, NB / BM), NTHREADS>>>(p_moe, wk, bk, p_k);
    gemm_kernel<false><<<dim3(NDM / BN, NB / BM), NTHREADS>>>(p_moe, wv, bv, p_v);

    attn_kernel<<<NB, 256>>>();

    gemm_kernel<false><<<dim3(NDM / BN, NB / BM), NTHREADS>>>(p_att, wo, bo, out);
}